// round 4
// baseline (speedup 1.0000x reference)
#include <cuda_runtime.h>
#include <cuda_bf16.h>

// GCN: 3-layer, N=100000 nodes, E=800000 edges.
// Restructure: A(hW) = (Ah)W  -> aggregate in the smaller dimension per layer.
// Self-loop contribution (norm = 1/deg) folded into per-node combine kernels.
// edge_index dtype (int32 vs int64) is sniffed at runtime (JAX silently
// downcasts int64 -> int32 unless x64 is enabled).

static constexpr int N = 100000;
static constexpr int E = 800000;

// ---------------- device scratch (static, no allocation) ----------------
__device__ float4 g_agg1[N];        // [N,4]   aggregated raw x
__device__ float4 g_h1[N * 32];     // [N,128] layer-1 activations
__device__ float4 g_t2[N * 16];     // [N,64]  h1 @ W2
__device__ float4 g_agg2[N * 16];   // [N,64]  aggregated t2; becomes h2 in-place
__device__ float  g_t3[N];          // [N]     h2 @ W3
__device__ float  g_deg[N];
__device__ float  g_dis[N];         // rsqrt(deg)
__device__ float  g_dis2[N];        // 1/deg  (self-loop norm)
__device__ int    g_src[E];
__device__ int    g_dst[E];
__device__ float  g_norm[E];
__device__ int    g_is64;           // 1 if edge_index is int64, 0 if int32

__device__ __forceinline__ void red_add_v4(float* p, float4 v) {
    asm volatile("red.global.add.v4.f32 [%0], {%1,%2,%3,%4};"
                 :: "l"(p), "f"(v.x), "f"(v.y), "f"(v.z), "f"(v.w)
                 : "memory");
}

// ---------------- kernels ----------------

// zero/initialize everything written by atomics this iteration
__global__ void k_init(float* __restrict__ out) {
    int i = blockIdx.x * blockDim.x + threadIdx.x;
    int stride = gridDim.x * blockDim.x;
    const float4 z4 = make_float4(0.f, 0.f, 0.f, 0.f);
    for (int j = i; j < N; j += stride) {
        g_deg[j] = 1.0f;            // self-loop weight
        g_agg1[j] = z4;
        out[j] = 0.0f;
    }
    for (int j = i; j < N * 16; j += stride) g_agg2[j] = z4;
}

// Sniff dtype: if edge buffer is int64 with values < 2^31, every odd int32
// word is 0. With real int32 data, odd words are edge indices (all-zero over
// 2048 samples is impossible for a random graph).
__global__ void k_detect(const int* __restrict__ ei32) {
    if (threadIdx.x != 0 || blockIdx.x != 0) return;
    unsigned acc = 0;
    for (int i = 1; i < 4096; i += 2) acc |= (unsigned)ei32[i];
    g_is64 = (acc == 0) ? 1 : 0;
}

// decode edge indices to int32 under either dtype; guard range
__global__ void k_decode(const int* __restrict__ ei32) {
    int e = blockIdx.x * blockDim.x + threadIdx.x;
    if (e >= E) return;
    int s, d;
    if (g_is64) {                    // little-endian low words
        s = ei32[2 * e];
        d = ei32[2 * (E + e)];
    } else {
        s = ei32[e];
        d = ei32[E + e];
    }
    if (s < 0 || s >= N) s = 0;      // safety: never fault
    if (d < 0 || d >= N) d = 0;
    g_src[e] = s;
    g_dst[e] = d;
}

// weighted in-degree
__global__ void k_deg(const float* __restrict__ w) {
    int e = blockIdx.x * blockDim.x + threadIdx.x;
    if (e >= E) return;
    atomicAdd(&g_deg[g_dst[e]], w[e]);
}

__global__ void k_dis() {
    int i = blockIdx.x * blockDim.x + threadIdx.x;
    if (i >= N) return;
    float dg = g_deg[i];
    g_dis[i]  = rsqrtf(dg);
    g_dis2[i] = 1.0f / dg;
}

// per-edge normalization coefficient
__global__ void k_norm(const float* __restrict__ w) {
    int e = blockIdx.x * blockDim.x + threadIdx.x;
    if (e >= E) return;
    g_norm[e] = g_dis[g_src[e]] * w[e] * g_dis[g_dst[e]];
}

// layer-1 aggregation in feature dim 4
__global__ void k_agg1(const float* __restrict__ x) {
    int e = blockIdx.x * blockDim.x + threadIdx.x;
    if (e >= E) return;
    int s = g_src[e], d = g_dst[e];
    float nr = g_norm[e];
    float4 v = ((const float4*)x)[s];
    v.x *= nr; v.y *= nr; v.z *= nr; v.w *= nr;
    red_add_v4((float*)&g_agg1[d], v);
}

// h1 = relu((agg1 + dis2*x) @ W1 + b1) ; one thread per (node, out-col)
__global__ void k_l1(const float* __restrict__ x, const float* __restrict__ W1,
                     const float* __restrict__ b1) {
    int idx = blockIdx.x * blockDim.x + threadIdx.x;
    if (idx >= N * 128) return;
    int i = idx >> 7, j = idx & 127;
    float4 a  = g_agg1[i];
    float4 xv = ((const float4*)x)[i];
    float s2  = g_dis2[i];
    float v0 = a.x + s2 * xv.x;
    float v1 = a.y + s2 * xv.y;
    float v2 = a.z + s2 * xv.z;
    float v3 = a.w + s2 * xv.w;
    float r = b1[j] + v0 * W1[j] + v1 * W1[128 + j] + v2 * W1[256 + j] + v3 * W1[384 + j];
    ((float*)g_h1)[idx] = fmaxf(r, 0.0f);
}

// t2 = h1 @ W2   (N x 128) @ (128 x 64); W2 in shared, 64 accumulators/thread
__global__ __launch_bounds__(128) void k_gemm2(const float* __restrict__ W2) {
    __shared__ float sW[128 * 64];
    for (int t = threadIdx.x; t < 128 * 64; t += blockDim.x) sW[t] = W2[t];
    __syncthreads();
    int node = blockIdx.x * blockDim.x + threadIdx.x;
    if (node >= N) return;

    float acc[64];
#pragma unroll
    for (int c = 0; c < 64; c++) acc[c] = 0.0f;

    const float4* hrow = &g_h1[node * 32];
#pragma unroll 1
    for (int k4 = 0; k4 < 32; k4++) {
        float4 a = hrow[k4];
        const float* w = &sW[k4 * 4 * 64];
#pragma unroll
        for (int c = 0; c < 64; c++) {
            acc[c] += a.x * w[c];
            acc[c] += a.y * w[64 + c];
            acc[c] += a.z * w[128 + c];
            acc[c] += a.w * w[192 + c];
        }
    }
    float4* out = &g_t2[node * 16];
#pragma unroll
    for (int c4 = 0; c4 < 16; c4++)
        out[c4] = make_float4(acc[4 * c4], acc[4 * c4 + 1], acc[4 * c4 + 2], acc[4 * c4 + 3]);
}

// layer-2 aggregation in feature dim 64: 16 threads (float4 chunks) per edge
__global__ void k_agg2() {
    int idx = blockIdx.x * blockDim.x + threadIdx.x;
    if (idx >= E * 16) return;
    int e = idx >> 4, c = idx & 15;
    int s = g_src[e], d = g_dst[e];
    float nr = g_norm[e];
    float4 v = g_t2[s * 16 + c];
    v.x *= nr; v.y *= nr; v.z *= nr; v.w *= nr;
    red_add_v4((float*)&g_agg2[d * 16 + c], v);
}

// h2 = relu(agg2 + dis2*t2 + b2), stored in-place into g_agg2
__global__ void k_l2(const float* __restrict__ b2) {
    int idx = blockIdx.x * blockDim.x + threadIdx.x;
    if (idx >= N * 64) return;
    int i = idx >> 6, j = idx & 63;
    float* a2 = (float*)g_agg2;
    const float* t2 = (const float*)g_t2;
    float r = a2[idx] + g_dis2[i] * t2[idx] + b2[j];
    a2[idx] = fmaxf(r, 0.0f);
}

// t3 = h2 @ W3 (dot of 64) ; one warp per node
__global__ void k_gemm3(const float* __restrict__ W3) {
    __shared__ float sw[64];
    if (threadIdx.x < 64) sw[threadIdx.x] = W3[threadIdx.x];
    __syncthreads();
    int gw = (blockIdx.x * blockDim.x + threadIdx.x) >> 5;
    int lane = threadIdx.x & 31;
    if (gw >= N) return;
    const float2* row = (const float2*)((const float*)g_agg2 + gw * 64);
    float2 v = row[lane];
    float p = v.x * sw[2 * lane] + v.y * sw[2 * lane + 1];
#pragma unroll
    for (int off = 16; off; off >>= 1) p += __shfl_down_sync(0xffffffffu, p, off);
    if (lane == 0) g_t3[gw] = p;
}

// layer-3 aggregation (scalar)
__global__ void k_agg3(float* __restrict__ out) {
    int e = blockIdx.x * blockDim.x + threadIdx.x;
    if (e >= E) return;
    atomicAdd(&out[g_dst[e]], g_norm[e] * g_t3[g_src[e]]);
}

// out += dis2*t3 + b3
__global__ void k_final(float* __restrict__ out, const float* __restrict__ b3) {
    int i = blockIdx.x * blockDim.x + threadIdx.x;
    if (i >= N) return;
    out[i] = out[i] + g_dis2[i] * g_t3[i] + b3[0];
}

// ---------------- launch ----------------
extern "C" void kernel_launch(void* const* d_in, const int* in_sizes, int n_in,
                              void* d_out, int out_size) {
    const float* x  = (const float*)d_in[0];
    const int*   ei = (const int*)d_in[1];      // int32 view; dtype sniffed on device
    const float* w  = (const float*)d_in[2];
    const float* W1 = (const float*)d_in[3];
    const float* b1 = (const float*)d_in[4];
    const float* W2 = (const float*)d_in[5];
    const float* b2 = (const float*)d_in[6];
    const float* W3 = (const float*)d_in[7];
    const float* b3 = (const float*)d_in[8];
    float* out = (float*)d_out;

    const int B = 256;

    k_init<<<2048, B>>>(out);
    k_detect<<<1, 32>>>(ei);
    k_decode<<<(E + B - 1) / B, B>>>(ei);
    k_deg<<<(E + B - 1) / B, B>>>(w);
    k_dis<<<(N + B - 1) / B, B>>>();
    k_norm<<<(E + B - 1) / B, B>>>(w);
    k_agg1<<<(E + B - 1) / B, B>>>(x);
    k_l1<<<(N * 128 + B - 1) / B, B>>>(x, W1, b1);
    k_gemm2<<<(N + 127) / 128, 128>>>(W2);
    k_agg2<<<(E * 16 + B - 1) / B, B>>>();
    k_l2<<<(N * 64 + B - 1) / B, B>>>(b2);
    k_gemm3<<<(N * 32 + B - 1) / B, B>>>(W3);   // 8 warps/block -> warp per node
    k_agg3<<<(E + B - 1) / B, B>>>(out);
    k_final<<<(N + B - 1) / B, B>>>(out, b3);
}

// round 5
// speedup vs baseline: 1.6435x; 1.6435x over previous
#include <cuda_runtime.h>
#include <cuda_bf16.h>

// GCN 3-layer, N=100000, E=800000. Aggregate in the smaller dim per layer.
// Self-loop (norm = 1/deg) folded into per-node combine steps.
// Fusions: decode+deg, norm+agg1, l1+gemm2 (h1 never materialized),
// l2+gemm3+final (h2 never materialized, out initialized here).

static constexpr int N = 100000;
static constexpr int E = 800000;

__device__ float4 g_agg1[N];        // [N,4]
__device__ float4 g_t2[N * 16];     // [N,64]  (x@W1->relu)@W2
__device__ float4 g_agg2[N * 16];   // [N,64]
__device__ float  g_t3[N];
__device__ float  g_deg[N];
__device__ float  g_dis[N];         // rsqrt(deg)
__device__ float  g_dis2[N];        // 1/deg
__device__ int    g_src[E];
__device__ int    g_dst[E];
__device__ float  g_norm[E];
__device__ int    g_is64;

__device__ __forceinline__ void red_add_v4(float* p, float4 v) {
    asm volatile("red.global.add.v4.f32 [%0], {%1,%2,%3,%4};"
                 :: "l"(p), "f"(v.x), "f"(v.y), "f"(v.z), "f"(v.w)
                 : "memory");
}

// ---------------- kernels ----------------

__global__ void k_init() {
    int i = blockIdx.x * blockDim.x + threadIdx.x;
    int stride = gridDim.x * blockDim.x;
    const float4 z4 = make_float4(0.f, 0.f, 0.f, 0.f);
    for (int j = i; j < N; j += stride) {
        g_deg[j] = 1.0f;            // self-loop weight
        g_agg1[j] = z4;
    }
    for (int j = i; j < N * 16; j += stride) g_agg2[j] = z4;
}

// dtype sniff: int64 values < 2^31 -> all odd int32 words zero.
__global__ void k_detect(const int* __restrict__ ei32) {
    __shared__ unsigned s[256];
    unsigned acc = 0;
    for (int i = threadIdx.x; i < 8192; i += 256) acc |= (unsigned)ei32[2 * i + 1];
    s[threadIdx.x] = acc;
    __syncthreads();
    for (int o = 128; o; o >>= 1) {
        if (threadIdx.x < o) s[threadIdx.x] |= s[threadIdx.x + o];
        __syncthreads();
    }
    if (threadIdx.x == 0) g_is64 = (s[0] == 0) ? 1 : 0;
}

// decode indices (either dtype) + weighted in-degree
__global__ void k_decode_deg(const int* __restrict__ ei32, const float* __restrict__ w) {
    int e = blockIdx.x * blockDim.x + threadIdx.x;
    if (e >= E) return;
    int s, d;
    if (g_is64) { s = ei32[2 * e]; d = ei32[2 * (E + e)]; }
    else        { s = ei32[e];     d = ei32[E + e]; }
    if ((unsigned)s >= (unsigned)N) s = 0;
    if ((unsigned)d >= (unsigned)N) d = 0;
    g_src[e] = s;
    g_dst[e] = d;
    atomicAdd(&g_deg[d], w[e]);
}

__global__ void k_dis() {
    int i = blockIdx.x * blockDim.x + threadIdx.x;
    if (i >= N) return;
    float dg = g_deg[i];
    g_dis[i]  = rsqrtf(dg);
    g_dis2[i] = 1.0f / dg;
}

// per-edge norm + layer-1 aggregation (dim 4)
__global__ void k_norm_agg1(const float* __restrict__ x, const float* __restrict__ w) {
    int e = blockIdx.x * blockDim.x + threadIdx.x;
    if (e >= E) return;
    int s = g_src[e], d = g_dst[e];
    float nr = g_dis[s] * w[e] * g_dis[d];
    g_norm[e] = nr;
    float4 v = ((const float4*)x)[s];
    v.x *= nr; v.y *= nr; v.z *= nr; v.w *= nr;
    red_add_v4((float*)&g_agg1[d], v);
}

// fused: h1_row = relu(v @ W1 + b1) streamed through registers; t2 = h1_row @ W2
__global__ __launch_bounds__(128) void k_l1gemm2(
    const float* __restrict__ x, const float* __restrict__ W1,
    const float* __restrict__ b1, const float* __restrict__ W2) {
    __shared__ float sW2[128 * 64];   // 32KB
    __shared__ float sW1[4 * 128];    // 2KB
    __shared__ float sb1[128];
    for (int t = threadIdx.x; t < 128 * 64; t += 128) sW2[t] = W2[t];
    for (int t = threadIdx.x; t < 4 * 128; t += 128)  sW1[t] = W1[t];
    if (threadIdx.x < 128) sb1[threadIdx.x] = b1[threadIdx.x];
    __syncthreads();

    int node = blockIdx.x * blockDim.x + threadIdx.x;
    if (node >= N) return;

    float4 ag = g_agg1[node];
    float4 xv = ((const float4*)x)[node];
    float s2 = g_dis2[node];
    float v0 = ag.x + s2 * xv.x;
    float v1 = ag.y + s2 * xv.y;
    float v2 = ag.z + s2 * xv.z;
    float v3 = ag.w + s2 * xv.w;

    float acc[64];
#pragma unroll
    for (int c = 0; c < 64; c++) acc[c] = 0.0f;

#pragma unroll 1
    for (int k4 = 0; k4 < 32; k4++) {
        // h1[k4*4 .. k4*4+3] on the fly
        float4 r0 = ((const float4*)sW1)[k4];            // W1[0][k..]
        float4 r1 = ((const float4*)(sW1 + 128))[k4];    // W1[1][k..]
        float4 r2 = ((const float4*)(sW1 + 256))[k4];
        float4 r3 = ((const float4*)(sW1 + 384))[k4];
        float4 bb = ((const float4*)sb1)[k4];
        float4 a;
        a.x = fmaxf(bb.x + v0 * r0.x + v1 * r1.x + v2 * r2.x + v3 * r3.x, 0.f);
        a.y = fmaxf(bb.y + v0 * r0.y + v1 * r1.y + v2 * r2.y + v3 * r3.y, 0.f);
        a.z = fmaxf(bb.z + v0 * r0.z + v1 * r1.z + v2 * r2.z + v3 * r3.z, 0.f);
        a.w = fmaxf(bb.w + v0 * r0.w + v1 * r1.w + v2 * r2.w + v3 * r3.w, 0.f);

        const float* w = &sW2[k4 * 4 * 64];
#pragma unroll
        for (int c = 0; c < 64; c++) {
            acc[c] += a.x * w[c];
            acc[c] += a.y * w[64 + c];
            acc[c] += a.z * w[128 + c];
            acc[c] += a.w * w[192 + c];
        }
    }
    float4* out = &g_t2[node * 16];
#pragma unroll
    for (int c4 = 0; c4 < 16; c4++)
        out[c4] = make_float4(acc[4 * c4], acc[4 * c4 + 1], acc[4 * c4 + 2], acc[4 * c4 + 3]);
}

// layer-2 aggregation in dim 64: 16 threads (float4 chunks) per edge
__global__ void k_agg2() {
    int idx = blockIdx.x * blockDim.x + threadIdx.x;
    if (idx >= E * 16) return;
    int e = idx >> 4, c = idx & 15;
    int s = g_src[e], d = g_dst[e];
    float nr = g_norm[e];
    float4 v = g_t2[s * 16 + c];
    v.x *= nr; v.y *= nr; v.z *= nr; v.w *= nr;
    red_add_v4((float*)&g_agg2[d * 16 + c], v);
}

// fused: h2 = relu(agg2 + dis2*t2 + b2); t3 = h2 . W3; out = dis2*t3 + b3
__global__ void k_l2gemm3(const float* __restrict__ b2, const float* __restrict__ W3,
                          const float* __restrict__ b3, float* __restrict__ out) {
    __shared__ float sw[64];
    __shared__ float sb2[64];
    if (threadIdx.x < 64) { sw[threadIdx.x] = W3[threadIdx.x]; sb2[threadIdx.x] = b2[threadIdx.x]; }
    __syncthreads();
    int gw = (blockIdx.x * blockDim.x + threadIdx.x) >> 5;
    int lane = threadIdx.x & 31;
    if (gw >= N) return;
    float s2 = g_dis2[gw];
    float2 a = ((const float2*)((const float*)g_agg2 + gw * 64))[lane];
    float2 t = ((const float2*)((const float*)g_t2   + gw * 64))[lane];
    float h0 = fmaxf(a.x + s2 * t.x + sb2[2 * lane],     0.f);
    float h1 = fmaxf(a.y + s2 * t.y + sb2[2 * lane + 1], 0.f);
    float p = h0 * sw[2 * lane] + h1 * sw[2 * lane + 1];
#pragma unroll
    for (int off = 16; off; off >>= 1) p += __shfl_down_sync(0xffffffffu, p, off);
    if (lane == 0) {
        g_t3[gw] = p;
        out[gw] = s2 * p + b3[0];   // self-loop + bias; edge atomics add on top
    }
}

// layer-3 aggregation (scalar atomics into out)
__global__ void k_agg3(float* __restrict__ out) {
    int e = blockIdx.x * blockDim.x + threadIdx.x;
    if (e >= E) return;
    atomicAdd(&out[g_dst[e]], g_norm[e] * g_t3[g_src[e]]);
}

// ---------------- launch ----------------
extern "C" void kernel_launch(void* const* d_in, const int* in_sizes, int n_in,
                              void* d_out, int out_size) {
    const float* x  = (const float*)d_in[0];
    const int*   ei = (const int*)d_in[1];      // dtype sniffed on device
    const float* w  = (const float*)d_in[2];
    const float* W1 = (const float*)d_in[3];
    const float* b1 = (const float*)d_in[4];
    const float* W2 = (const float*)d_in[5];
    const float* b2 = (const float*)d_in[6];
    const float* W3 = (const float*)d_in[7];
    const float* b3 = (const float*)d_in[8];
    float* out = (float*)d_out;

    const int B = 256;

    k_init<<<2048, B>>>();
    k_detect<<<1, 256>>>(ei);
    k_decode_deg<<<(E + B - 1) / B, B>>>(ei, w);
    k_dis<<<(N + B - 1) / B, B>>>();
    k_norm_agg1<<<(E + B - 1) / B, B>>>(x, w);
    k_l1gemm2<<<(N + 127) / 128, 128>>>(x, W1, b1, W2);
    k_agg2<<<(E * 16 + B - 1) / B, B>>>();
    k_l2gemm3<<<(N * 32 + B - 1) / B, B>>>(b2, W3, b3, out);
    k_agg3<<<(E + B - 1) / B, B>>>(out);
}